// round 4
// baseline (speedup 1.0000x reference)
#include <cuda_runtime.h>

#define NF 24
#define ED 16
#define AS 32
#define AH 16      /* AS/2 */
#define NPAIR 276
#define TPB 96
#define PPT 3
#define ACTIVE_T 92

__device__ int g_x64_flag;

// Detect whether x is int64 or int32: for int64 little-endian with values in
// [0, 50000), every odd 32-bit word is 0. For int32 random values, the chance
// all 64 sampled odd words are 0 is ~(2e-5)^64 ~ 0.
__global__ void detect_dtype_kernel(const unsigned int* __restrict__ xraw) {
    if (threadIdx.x == 0) {
        unsigned int acc = 0;
        #pragma unroll 1
        for (int k = 0; k < 64; k++) acc |= xraw[2 * k + 1];
        g_x64_flag = (acc == 0u) ? 1 : 0;
    }
}

__device__ __forceinline__ unsigned long long fma2(unsigned long long a,
                                                   unsigned long long b,
                                                   unsigned long long c) {
    unsigned long long d;
    asm("fma.rn.f32x2 %0, %1, %2, %3;" : "=l"(d) : "l"(a), "l"(b), "l"(c));
    return d;
}
__device__ __forceinline__ unsigned long long pack2(float x) {
    unsigned long long d;
    asm("mov.b64 %0, {%1, %1};" : "=l"(d) : "f"(x));
    return d;
}
__device__ __forceinline__ void unpack2(unsigned long long v, float& lo, float& hi) {
    asm("mov.b64 {%0, %1}, %2;" : "=f"(lo), "=f"(hi) : "l"(v));
}

__global__ __launch_bounds__(TPB) void afm_kernel(
    const void* __restrict__ xraw,
    const float* __restrict__ embed_table,
    const float* __restrict__ linear_table,
    const float* __restrict__ linear_bias,
    const float* __restrict__ attn_W,
    const float* __restrict__ attn_b,
    const float* __restrict__ proj_w,
    const float* __restrict__ proj_b,
    const float* __restrict__ fc_w,
    const float* __restrict__ fc_b,
    float* __restrict__ out)
{
    __shared__ float s_emb[ED][NF];                 // [e][f] — conflict-free pair reads
    __shared__ unsigned long long s_W2[ED][AH];     // W packed as (a, a+1) float2
    __shared__ unsigned long long s_bias2[AH];      // attn_b packed pairs
    __shared__ float s_proj[AS];
    __shared__ int   s_gidx[NF];
    __shared__ float s_lin[NF];
    __shared__ float s_m[PPT];                      // per-warp max
    __shared__ float s_s[PPT];                      // per-warp exp-sum
    __shared__ float s_pool[PPT][ED];               // per-warp pooled partials

    const int b   = blockIdx.x;
    const int tid = threadIdx.x;
    const int wid = tid >> 5;
    const int lid = tid & 31;

    // ---- stage indices, linear terms, weights into smem ----
    if (tid < NF) {
        long long xv;
        if (g_x64_flag) xv = ((const long long*)xraw)[(long long)b * NF + tid];
        else            xv = (long long)((const int*)xraw)[b * NF + tid];
        int g = (int)xv + tid * 50000;
        s_gidx[tid] = g;
        s_lin[tid]  = linear_table[g];
    }
    {
        const unsigned long long* Wsrc = (const unsigned long long*)attn_W;
        #pragma unroll
        for (int i = tid; i < ED * AH; i += TPB)
            ((unsigned long long*)s_W2)[i] = Wsrc[i];
    }
    if (tid < AH)  s_bias2[tid] = ((const unsigned long long*)attn_b)[tid];
    if (tid < AS)  s_proj[tid]  = proj_w[tid];
    __syncthreads();

    // ---- gather embeddings: consecutive threads read consecutive e (64B coalesced)
    #pragma unroll
    for (int i = tid; i < NF * ED; i += TPB) {
        int f = i >> 4, e = i & 15;
        s_emb[e][f] = embed_table[(long long)s_gidx[f] * ED + e];
    }
    __syncthreads();

    // ---- pair setup: thread handles pairs p = 3*tid .. 3*tid+2 ----
    const bool active = (tid < ACTIVE_T);
    float inner[PPT][ED];
    #pragma unroll
    for (int q = 0; q < PPT; q++) {
        int p = active ? (tid * PPT + q) : 0;
        int r = 0, rem = p;
        while (rem >= 23 - r) { rem -= 23 - r; r++; }
        int c = r + 1 + rem;
        #pragma unroll
        for (int e = 0; e < ED; e++)
            inner[q][e] = s_emb[e][r] * s_emb[e][c];
    }

    // ---- h = relu(inner @ W + b): packed f32x2 FMAs, W LDS amortized over 3 pairs
    unsigned long long acc[PPT][AH];
    #pragma unroll
    for (int q = 0; q < PPT; q++)
        #pragma unroll
        for (int a = 0; a < AH; a++)
            acc[q][a] = s_bias2[a];

    #pragma unroll
    for (int e = 0; e < ED; e++) {
        unsigned long long w[AH];
        #pragma unroll
        for (int a = 0; a < AH; a++) w[a] = s_W2[e][a];
        #pragma unroll
        for (int q = 0; q < PPT; q++) {
            unsigned long long bb = pack2(inner[q][e]);
            #pragma unroll
            for (int a = 0; a < AH; a++)
                acc[q][a] = fma2(bb, w[a], acc[q][a]);
        }
    }

    // ---- scores = relu(h) . proj_w + proj_b ----
    const float pb = proj_b[0];
    float sc[PPT];
    #pragma unroll
    for (int q = 0; q < PPT; q++) {
        float s = 0.f;
        #pragma unroll
        for (int a = 0; a < AH; a++) {
            float lo, hi;
            unpack2(acc[q][a], lo, hi);
            lo = fmaxf(lo, 0.f);
            hi = fmaxf(hi, 0.f);
            s = fmaf(lo, s_proj[2 * a], s);
            s = fmaf(hi, s_proj[2 * a + 1], s);
        }
        sc[q] = s + pb;
    }

    // ---- softmax max (warp shfl + cross-warp smem) ----
    float m = active ? fmaxf(fmaxf(sc[0], sc[1]), sc[2]) : -1e30f;
    #pragma unroll
    for (int o = 16; o > 0; o >>= 1)
        m = fmaxf(m, __shfl_xor_sync(0xffffffffu, m, o));
    if (lid == 0) s_m[wid] = m;
    __syncthreads();
    const float M = fmaxf(fmaxf(s_m[0], s_m[1]), s_m[2]);

    // ---- exp weights (unnormalized; divide once at the end) ----
    float ex[PPT];
    float lsum = 0.f;
    #pragma unroll
    for (int q = 0; q < PPT; q++) {
        ex[q] = active ? __expf(sc[q] - M) : 0.f;
        lsum += ex[q];
    }

    // ---- pooled = sum_p ex_p * inner_p  (then /S at the end) ----
    float v[ED];
    #pragma unroll
    for (int e = 0; e < ED; e++)
        v[e] = fmaf(ex[0], inner[0][e], fmaf(ex[1], inner[1][e], ex[2] * inner[2][e]));

    #pragma unroll
    for (int o = 16; o > 0; o >>= 1) {
        lsum += __shfl_xor_sync(0xffffffffu, lsum, o);
        #pragma unroll
        for (int e = 0; e < ED; e++)
            v[e] += __shfl_xor_sync(0xffffffffu, v[e], o);
    }
    if (lid == 0) {
        s_s[wid] = lsum;
        #pragma unroll
        for (int e = 0; e < ED; e++) s_pool[wid][e] = v[e];
    }
    __syncthreads();

    // ---- final output (one thread) ----
    if (tid == 0) {
        float S = s_s[0] + s_s[1] + s_s[2];
        float cross = 0.f;
        #pragma unroll
        for (int e = 0; e < ED; e++) {
            float pe = s_pool[0][e] + s_pool[1][e] + s_pool[2][e];
            cross = fmaf(pe, fc_w[e], cross);
        }
        float lin = 0.f;
        #pragma unroll
        for (int f = 0; f < NF; f++) lin += s_lin[f];
        out[b] = lin + linear_bias[0] + cross / S + fc_b[0];
    }
}

extern "C" void kernel_launch(void* const* d_in, const int* in_sizes, int n_in,
                              void* d_out, int out_size) {
    const void*  x            = d_in[0];
    const float* embed_table  = (const float*)d_in[1];
    const float* linear_table = (const float*)d_in[2];
    const float* linear_bias  = (const float*)d_in[3];
    const float* attn_W       = (const float*)d_in[4];
    const float* attn_b       = (const float*)d_in[5];
    const float* proj_w       = (const float*)d_in[6];
    const float* proj_b       = (const float*)d_in[7];
    const float* fc_w         = (const float*)d_in[8];
    const float* fc_b         = (const float*)d_in[9];
    float* out = (float*)d_out;

    int B = in_sizes[0] / NF;

    detect_dtype_kernel<<<1, 32>>>((const unsigned int*)x);
    afm_kernel<<<B, TPB>>>(x, embed_table, linear_table, linear_bias,
                           attn_W, attn_b, proj_w, proj_b, fc_w, fc_b, out);
}